// round 2
// baseline (speedup 1.0000x reference)
#include <cuda_runtime.h>
#include <math.h>

// Problem constants (fixed shapes)
#define BB   8
#define CC   512
#define LL   8192
#define NN   512        // LL / 16 chunks
#define CO   64         // CC / 8
#define CS   16

// Scratch (allocation-free rule: __device__ globals)
__device__ float g_e[BB * CC * NN];      // EMA output  [B][C][N]  (8 MB)
__device__ float g_gate[BB * CC * NN];   // sigmoid out [B][C][N]  (16 MB total w/ e)

// ---------------------------------------------------------------------------
// Kernel 1: chunk mean + causal EMA scan.
// One block per (b,c) row. 512 threads, one chunk each.
// y_t = g*y_{t-1} + (1-g)*mean_t  computed as an affine parallel scan.
// ---------------------------------------------------------------------------
__global__ __launch_bounds__(512) void k_mean_ema(const float* __restrict__ x,
                                                  const float* __restrict__ gamma) {
    const int row = blockIdx.x;            // b*CC + c
    const int c   = row & (CC - 1);
    const int t   = threadIdx.x;

    const float4* xr = reinterpret_cast<const float4*>(x) + (size_t)row * (LL / 4);

    __shared__ __align__(16) float f4sum[LL / 4];   // 2048 floats = 8 KB
    __shared__ float wa[16], wb[16];

    // Coalesced loads: thread t loads float4 indices t, t+512, t+1024, t+1536
#pragma unroll
    for (int k = 0; k < 4; k++) {
        float4 v = xr[t + 512 * k];
        f4sum[t + 512 * k] = v.x + v.y + v.z + v.w;
    }
    __syncthreads();

    // chunk t = float4 partials 4t..4t+3 (LDS.128, conflict-free)
    float4 cs = reinterpret_cast<const float4*>(f4sum)[t];
    float mean = (cs.x + cs.y + cs.z + cs.w) * (1.0f / 16.0f);

    const float g = gamma[c];
    // affine transform y -> a*y + b
    float a  = g;
    float bb = (1.0f - g) * mean;

    const int lane = t & 31, warp = t >> 5;
    // inclusive warp scan of affine composition (later ∘ earlier)
#pragma unroll
    for (int off = 1; off < 32; off <<= 1) {
        float pa = __shfl_up_sync(0xffffffffu, a,  off);
        float pb = __shfl_up_sync(0xffffffffu, bb, off);
        if (lane >= off) { bb = a * pb + bb; a = a * pa; }
    }
    if (lane == 31) { wa[warp] = a; wb[warp] = bb; }
    __syncthreads();

    // serial fixup over preceding warps (<=15 iterations, smem broadcast)
    float prevB = 0.0f;                    // y after warps 0..warp-1, with y_{-1}=0
    for (int w = 0; w < warp; w++) prevB = wa[w] * prevB + wb[w];

    float y = a * prevB + bb;              // y_t with zero initial state
    g_e[(size_t)row * NN + t] = y;
}

// ---------------------------------------------------------------------------
// Kernel 2 (fused SE): gate = sigmoid(w2 @ relu(w1 @ e + b1) + b2)
// One block per (batch, 32-chunk n-tile). 256 threads.
// Phase A: h[64 x 32] = relu(w1[64x512] @ e[512x32] + b1)  -> smem
// Phase B: for each of 8 c-tiles: gate[64 x 32] = sigmoid(w2 @ h + b2)
// ---------------------------------------------------------------------------
__global__ __launch_bounds__(256) void k_se(const float* __restrict__ w1,
                                            const float* __restrict__ b1,
                                            const float* __restrict__ w2,
                                            const float* __restrict__ b2) {
    const int b  = blockIdx.y;
    const int n0 = blockIdx.x * 32;
    const float* e = g_e + (size_t)b * CC * NN;

    __shared__ __align__(16) float se [64 * 36];  // input tile [k][n], pad 36
    __shared__ float             swt[64 * 65];    // weight tile transposed [k][out]
    __shared__ __align__(16) float sh [64 * 36];  // h tile [o][n], pad 36

    const int t  = threadIdx.x;
    const int nx = t & 7;        // n = n0 + nx*4 + j   (j = 0..3)
    const int ox = t >> 3;       // out pair: o = ox*2 + i  (ox = 0..31)

    // ---------- Phase A: GEMM1 ----------
    float acc[2][4] = {};

    for (int c0 = 0; c0 < CC; c0 += 64) {
        // stage e[64cc x 32n] — coalesced along n (2048 elems, 8/thread)
#pragma unroll
        for (int i = 0; i < 8; i++) {
            int idx = t + i * 256;
            int cc = idx >> 5, nn = idx & 31;
            se[cc * 36 + nn] = e[(size_t)(c0 + cc) * NN + n0 + nn];
        }
        // stage w1[o][c0+cc] -> swt[cc][o]  (4096 elems, 16/thread, coalesced along cc)
#pragma unroll
        for (int i = 0; i < 16; i++) {
            int idx = t + i * 256;
            int o = idx >> 6, cc = idx & 63;
            swt[cc * 65 + o] = w1[(size_t)o * CC + c0 + cc];
        }
        __syncthreads();

#pragma unroll
        for (int cc = 0; cc < 64; cc++) {
            float4 bv = *reinterpret_cast<const float4*>(&se[cc * 36 + nx * 4]);
            float a0 = swt[cc * 65 + ox * 2 + 0];
            float a1 = swt[cc * 65 + ox * 2 + 1];
            acc[0][0] += a0 * bv.x; acc[0][1] += a0 * bv.y; acc[0][2] += a0 * bv.z; acc[0][3] += a0 * bv.w;
            acc[1][0] += a1 * bv.x; acc[1][1] += a1 * bv.y; acc[1][2] += a1 * bv.z; acc[1][3] += a1 * bv.w;
        }
        __syncthreads();
    }

    // h -> smem with bias + relu
#pragma unroll
    for (int i = 0; i < 2; i++) {
        int o = ox * 2 + i;
        float bias = b1[o];
        float4 v;
        v.x = fmaxf(acc[i][0] + bias, 0.0f);
        v.y = fmaxf(acc[i][1] + bias, 0.0f);
        v.z = fmaxf(acc[i][2] + bias, 0.0f);
        v.w = fmaxf(acc[i][3] + bias, 0.0f);
        *reinterpret_cast<float4*>(&sh[o * 36 + nx * 4]) = v;
    }
    __syncthreads();

    // ---------- Phase B: GEMM2, 8 c-tiles of 64 ----------
    float* gate = g_gate + (size_t)b * CC * NN;

    for (int cb = 0; cb < 8; cb++) {
        const int c0 = cb * 64;
        // stage w2[(c0+c)][k] -> swt[k][c]  (4096 elems, 16/thread, coalesced along k)
#pragma unroll
        for (int i = 0; i < 16; i++) {
            int idx = t + i * 256;
            int c = idx >> 6, k = idx & 63;
            swt[k * 65 + c] = w2[(size_t)(c0 + c) * CO + k];
        }
        __syncthreads();

        float a2[2][4] = {};
#pragma unroll
        for (int k = 0; k < 64; k++) {
            float4 bv = *reinterpret_cast<const float4*>(&sh[k * 36 + nx * 4]);
            float a0 = swt[k * 65 + ox * 2 + 0];
            float a1 = swt[k * 65 + ox * 2 + 1];
            a2[0][0] += a0 * bv.x; a2[0][1] += a0 * bv.y; a2[0][2] += a0 * bv.z; a2[0][3] += a0 * bv.w;
            a2[1][0] += a1 * bv.x; a2[1][1] += a1 * bv.y; a2[1][2] += a1 * bv.z; a2[1][3] += a1 * bv.w;
        }

#pragma unroll
        for (int i = 0; i < 2; i++) {
            int c = c0 + ox * 2 + i;
            float bias = b2[c];
            float4 v;
            v.x = 1.0f / (1.0f + __expf(-(a2[i][0] + bias)));
            v.y = 1.0f / (1.0f + __expf(-(a2[i][1] + bias)));
            v.z = 1.0f / (1.0f + __expf(-(a2[i][2] + bias)));
            v.w = 1.0f / (1.0f + __expf(-(a2[i][3] + bias)));
            *reinterpret_cast<float4*>(&gate[(size_t)c * NN + n0 + nx * 4]) = v;
        }
        __syncthreads();   // protect swt before next c-tile staging
    }
}

// ---------------------------------------------------------------------------
// Kernel 3: out = repeat(gate, 16) * x   (float4 streaming)
// Flat float4 index i over [B][C][L/4]; gate flat index = i >> 2.
// ---------------------------------------------------------------------------
__global__ __launch_bounds__(256) void k_apply(const float* __restrict__ x,
                                               float* __restrict__ out) {
    size_t i = (size_t)blockIdx.x * blockDim.x + threadIdx.x;   // float4 index
    float4 v = reinterpret_cast<const float4*>(x)[i];
    float g = g_gate[i >> 2];
    float4 o;
    o.x = v.x * g; o.y = v.y * g; o.z = v.z * g; o.w = v.w * g;
    reinterpret_cast<float4*>(out)[i] = o;
}

// ---------------------------------------------------------------------------
extern "C" void kernel_launch(void* const* d_in, const int* in_sizes, int n_in,
                              void* d_out, int out_size) {
    const float* x     = (const float*)d_in[0];
    const float* gamma = (const float*)d_in[1];
    const float* w1    = (const float*)d_in[2];
    const float* b1    = (const float*)d_in[3];
    const float* w2    = (const float*)d_in[4];
    const float* b2    = (const float*)d_in[5];
    float* out = (float*)d_out;

    k_mean_ema<<<BB * CC, 512>>>(x, gamma);
    k_se<<<dim3(NN / 32, BB), 256>>>(w1, b1, w2, b2);

    const size_t nf4 = (size_t)BB * CC * LL / 4;   // 8,388,608 float4
    k_apply<<<(unsigned)(nf4 / 256), 256>>>(x, out);
}